// round 2
// baseline (speedup 1.0000x reference)
#include <cuda_runtime.h>
#include <cuda_bf16.h>
#include <mma.h>
#include <math.h>

using namespace nvcuda;

// Problem dims
#define NTOK   204800          // B*T*V = 64*128*25
#define NSEQ   8192            // B*T
#define SEQ    25
#define DMODEL 256
#define NHEAD  8
#define HDIM   32
#define DFFN   1024
#define D3     768

// ------------------------- scratch (device globals) -------------------------
__device__ __nv_bfloat16 g_yb  [(size_t)NTOK * DMODEL];   // LN1 output, bf16
__device__ __nv_bfloat16 g_qkv [(size_t)NTOK * D3];       // qkv, bf16
__device__ __nv_bfloat16 g_attn[(size_t)NTOK * DMODEL];   // attention out, bf16
__device__ float         g_x2  [(size_t)NTOK * DMODEL];   // residual after proj, fp32
__device__ __nv_bfloat16 g_y2  [(size_t)NTOK * DMODEL];   // LN2 output, bf16
__device__ __nv_bfloat16 g_hid [(size_t)NTOK * DFFN];     // ffn hidden, bf16
__device__ __nv_bfloat16 g_wqkv[DMODEL * D3];
__device__ __nv_bfloat16 g_wproj[DMODEL * DMODEL];
__device__ __nv_bfloat16 g_w1  [DMODEL * DFFN];
__device__ __nv_bfloat16 g_w2  [DFFN * DMODEL];

// ------------------------- weight fp32 -> bf16 -------------------------
__global__ void convert_w_kernel(const float* __restrict__ qkv_w,
                                 const float* __restrict__ proj_w,
                                 const float* __restrict__ w1,
                                 const float* __restrict__ w2) {
    int i0 = blockIdx.x * blockDim.x + threadIdx.x;
    int stride = gridDim.x * blockDim.x;
    for (int i = i0; i < DMODEL * D3; i += stride)     g_wqkv[i]  = __float2bfloat16(qkv_w[i]);
    for (int i = i0; i < DMODEL * DMODEL; i += stride) g_wproj[i] = __float2bfloat16(proj_w[i]);
    for (int i = i0; i < DMODEL * DFFN; i += stride)   g_w1[i]    = __float2bfloat16(w1[i]);
    for (int i = i0; i < DFFN * DMODEL; i += stride)   g_w2[i]    = __float2bfloat16(w2[i]);
}

// ------------------------- LayerNorm (warp per row, D=256) -------------------------
__global__ __launch_bounds__(256) void ln_kernel(const float* __restrict__ X,
                                                 const float* __restrict__ gam,
                                                 const float* __restrict__ bet,
                                                 __nv_bfloat16* __restrict__ Y) {
    int warp = (blockIdx.x * blockDim.x + threadIdx.x) >> 5;
    int lane = threadIdx.x & 31;
    if (warp >= NTOK) return;
    const float4* xp = (const float4*)(X + (size_t)warp * DMODEL);
    float4 v0 = xp[lane * 2];
    float4 v1 = xp[lane * 2 + 1];
    float s = v0.x + v0.y + v0.z + v0.w + v1.x + v1.y + v1.z + v1.w;
    #pragma unroll
    for (int o = 16; o > 0; o >>= 1) s += __shfl_xor_sync(0xffffffffu, s, o);
    float m = s * (1.0f / 256.0f);
    float d0x = v0.x - m, d0y = v0.y - m, d0z = v0.z - m, d0w = v0.w - m;
    float d1x = v1.x - m, d1y = v1.y - m, d1z = v1.z - m, d1w = v1.w - m;
    float vs = d0x*d0x + d0y*d0y + d0z*d0z + d0w*d0w + d1x*d1x + d1y*d1y + d1z*d1z + d1w*d1w;
    #pragma unroll
    for (int o = 16; o > 0; o >>= 1) vs += __shfl_xor_sync(0xffffffffu, vs, o);
    float rstd = rsqrtf(vs * (1.0f / 256.0f) + 1e-5f);
    const float4* gp = (const float4*)gam;
    const float4* bp = (const float4*)bet;
    float4 g0 = gp[lane * 2], g1 = gp[lane * 2 + 1];
    float4 b0 = bp[lane * 2], b1 = bp[lane * 2 + 1];
    float y[8];
    y[0] = d0x * rstd * g0.x + b0.x;  y[1] = d0y * rstd * g0.y + b0.y;
    y[2] = d0z * rstd * g0.z + b0.z;  y[3] = d0w * rstd * g0.w + b0.w;
    y[4] = d1x * rstd * g1.x + b1.x;  y[5] = d1y * rstd * g1.y + b1.y;
    y[6] = d1z * rstd * g1.z + b1.z;  y[7] = d1w * rstd * g1.w + b1.w;
    union { int4 i4; __nv_bfloat162 h2[4]; } u;
    u.h2[0] = __floats2bfloat162_rn(y[0], y[1]);
    u.h2[1] = __floats2bfloat162_rn(y[2], y[3]);
    u.h2[2] = __floats2bfloat162_rn(y[4], y[5]);
    u.h2[3] = __floats2bfloat162_rn(y[6], y[7]);
    *((int4*)(Y + (size_t)warp * DMODEL + lane * 8)) = u.i4;
}

// ------------------------- GEMM (bf16 WMMA, 64x64 tile, 4 warps) -------------------------
// C[M,N] = A[M,K] @ B[K,N] + bias, with epilogue variants. M fixed = NTOK.
enum { EPI_BF16 = 0, EPI_PROJ = 1, EPI_GELU = 2, EPI_OUT = 3 };

template <int EPI>
__global__ __launch_bounds__(128) void gemm_kernel(
    const __nv_bfloat16* __restrict__ A,
    const __nv_bfloat16* __restrict__ B,
    const float* __restrict__ bias,
    const float* __restrict__ res,
    void* __restrict__ out,
    int N, int K)
{
    __shared__ __nv_bfloat16 As[64][40];
    __shared__ __nv_bfloat16 Bs[32][72];
    __shared__ float Cs[64 * 68];

    int t = threadIdx.x;
    int warp = t >> 5;
    int wm = warp >> 1;      // 0..1
    int wn = warp & 1;       // 0..1
    size_t m0 = (size_t)blockIdx.x * 64;
    int n0 = blockIdx.y * 64;

    wmma::fragment<wmma::accumulator, 16, 16, 16, float> c[2][2];
    #pragma unroll
    for (int i = 0; i < 2; i++)
        #pragma unroll
        for (int j = 0; j < 2; j++) wmma::fill_fragment(c[i][j], 0.0f);

    for (int k0 = 0; k0 < K; k0 += 32) {
        // A tile: 64x32.  thread -> row t/2, 16-col chunk (t&1)*16
        {
            int r = t >> 1, cs = (t & 1) * 16;
            const int4* src = (const int4*)(A + (m0 + r) * K + k0 + cs);
            int4* dst = (int4*)(&As[r][cs]);
            dst[0] = src[0];
            dst[1] = src[1];
        }
        // B tile: 32x64.  thread -> row t/4, 16-col chunk (t&3)*16
        {
            int r = t >> 2, cs = (t & 3) * 16;
            const int4* src = (const int4*)(B + (size_t)(k0 + r) * N + n0 + cs);
            int4* dst = (int4*)(&Bs[r][cs]);
            dst[0] = src[0];
            dst[1] = src[1];
        }
        __syncthreads();
        #pragma unroll
        for (int kk = 0; kk < 32; kk += 16) {
            wmma::fragment<wmma::matrix_a, 16, 16, 16, __nv_bfloat16, wmma::row_major> af[2];
            wmma::fragment<wmma::matrix_b, 16, 16, 16, __nv_bfloat16, wmma::row_major> bf[2];
            #pragma unroll
            for (int i = 0; i < 2; i++)
                wmma::load_matrix_sync(af[i], &As[wm * 32 + i * 16][kk], 40);
            #pragma unroll
            for (int j = 0; j < 2; j++)
                wmma::load_matrix_sync(bf[j], &Bs[kk][wn * 32 + j * 16], 72);
            #pragma unroll
            for (int i = 0; i < 2; i++)
                #pragma unroll
                for (int j = 0; j < 2; j++)
                    wmma::mma_sync(c[i][j], af[i], bf[j], c[i][j]);
        }
        __syncthreads();
    }

    #pragma unroll
    for (int i = 0; i < 2; i++)
        #pragma unroll
        for (int j = 0; j < 2; j++)
            wmma::store_matrix_sync(&Cs[(wm * 32 + i * 16) * 68 + wn * 32 + j * 16],
                                    c[i][j], 68, wmma::mem_row_major);
    __syncthreads();

    for (int e = t; e < 4096; e += 128) {
        int r = e >> 6, cc = e & 63;
        float v = Cs[r * 68 + cc];
        size_t gr = m0 + r;
        int gc = n0 + cc;
        v += bias[gc];
        size_t oidx = gr * N + gc;
        if (EPI == EPI_BF16) {
            ((__nv_bfloat16*)out)[oidx] = __float2bfloat16(v);
        } else if (EPI == EPI_GELU) {
            v = 0.5f * v * (1.0f + erff(v * 0.70710678118654752f));
            ((__nv_bfloat16*)out)[oidx] = __float2bfloat16(v);
        } else if (EPI == EPI_PROJ) {
            v += res[oidx];
            ((float*)out)[oidx] = v;
        } else {  // EPI_OUT
            v += res[oidx];
            ((float*)out)[oidx] = v;
        }
    }
}

// ------------------------- Cosine attention (block per sequence, warp per head) -------------------------
// q,k,v are 25x32 per head. Lane i (<25) owns row i.
__global__ __launch_bounds__(256) void attn_kernel(const float* __restrict__ logit_scale) {
    extern __shared__ float sm[];
    float* k_s = sm;                       // [8][25][32]
    float* v_s = sm + NHEAD * SEQ * HDIM;  // [8][25][32]

    int n = blockIdx.x;
    int h = threadIdx.x >> 5;
    int lane = threadIdx.x & 31;

    const __nv_bfloat16* base = g_qkv + (size_t)n * SEQ * D3;
    float* kh = k_s + h * SEQ * HDIM;
    float* vh = v_s + h * SEQ * HDIM;

    float scale = expf(fminf(logit_scale[h], 4.6051701859880914f));  // log(100)

    float q[32];
    if (lane < SEQ) {
        const __nv_bfloat16* qp = base + (size_t)lane * D3 + h * HDIM;
        const __nv_bfloat16* kp = qp + DMODEL;
        const __nv_bfloat16* vp = qp + 2 * DMODEL;
        float kr[32];
        float qs = 0.0f, ks = 0.0f;
        #pragma unroll
        for (int d = 0; d < 32; d++) {
            q[d] = __bfloat162float(qp[d]);
            qs += q[d] * q[d];
            kr[d] = __bfloat162float(kp[d]);
            ks += kr[d] * kr[d];
        }
        // fold head temperature and 1/sqrt(head_dim) into q's normalization
        float qf = scale * 0.17677669529663687f / fmaxf(sqrtf(qs), 1e-12f);  // 1/sqrt(32)
        float kf = 1.0f / fmaxf(sqrtf(ks), 1e-12f);
        #pragma unroll
        for (int d = 0; d < 32; d++) {
            q[d] *= qf;
            kh[lane * 32 + d] = kr[d] * kf;
            vh[lane * 32 + d] = __bfloat162float(vp[d]);
        }
    }
    __syncwarp();

    if (lane < SEQ) {
        float lg[SEQ];
        float mx = -1e30f;
        #pragma unroll
        for (int j = 0; j < SEQ; j++) {
            const float4* kp4 = (const float4*)(kh + j * 32);
            float dot = 0.0f;
            #pragma unroll
            for (int tt = 0; tt < 8; tt++) {
                float4 kv = kp4[tt];
                dot += q[tt * 4 + 0] * kv.x + q[tt * 4 + 1] * kv.y
                     + q[tt * 4 + 2] * kv.z + q[tt * 4 + 3] * kv.w;
            }
            lg[j] = dot;
            mx = fmaxf(mx, dot);
        }
        float ssum = 0.0f;
        #pragma unroll
        for (int j = 0; j < SEQ; j++) {
            lg[j] = expf(lg[j] - mx);
            ssum += lg[j];
        }
        float inv = 1.0f / ssum;

        float acc[32];
        #pragma unroll
        for (int d = 0; d < 32; d++) acc[d] = 0.0f;
        #pragma unroll
        for (int j = 0; j < SEQ; j++) {
            float a = lg[j];
            const float4* vp4 = (const float4*)(vh + j * 32);
            #pragma unroll
            for (int tt = 0; tt < 8; tt++) {
                float4 vv = vp4[tt];
                acc[tt * 4 + 0] += a * vv.x;
                acc[tt * 4 + 1] += a * vv.y;
                acc[tt * 4 + 2] += a * vv.z;
                acc[tt * 4 + 3] += a * vv.w;
            }
        }
        __nv_bfloat162* op = (__nv_bfloat162*)(g_attn + ((size_t)n * SEQ + lane) * DMODEL + h * HDIM);
        #pragma unroll
        for (int tt = 0; tt < 16; tt++)
            op[tt] = __floats2bfloat162_rn(acc[2 * tt] * inv, acc[2 * tt + 1] * inv);
    }
}

// ------------------------- launch -------------------------
extern "C" void kernel_launch(void* const* d_in, const int* in_sizes, int n_in,
                              void* d_out, int out_size) {
    const float* x           = (const float*)d_in[0];
    const float* ln1_g       = (const float*)d_in[1];
    const float* ln1_b       = (const float*)d_in[2];
    const float* qkv_w       = (const float*)d_in[3];
    const float* qkv_b       = (const float*)d_in[4];
    const float* proj_w      = (const float*)d_in[5];
    const float* proj_b      = (const float*)d_in[6];
    const float* logit_scale = (const float*)d_in[7];
    const float* ln2_g       = (const float*)d_in[8];
    const float* ln2_b       = (const float*)d_in[9];
    const float* w1          = (const float*)d_in[10];
    const float* b1          = (const float*)d_in[11];
    const float* w2          = (const float*)d_in[12];
    const float* b2          = (const float*)d_in[13];
    float* out = (float*)d_out;

    void *p_yb, *p_qkv, *p_attn, *p_x2, *p_y2, *p_hid, *p_wqkv, *p_wproj, *p_w1, *p_w2;
    cudaGetSymbolAddress(&p_yb, g_yb);
    cudaGetSymbolAddress(&p_qkv, g_qkv);
    cudaGetSymbolAddress(&p_attn, g_attn);
    cudaGetSymbolAddress(&p_x2, g_x2);
    cudaGetSymbolAddress(&p_y2, g_y2);
    cudaGetSymbolAddress(&p_hid, g_hid);
    cudaGetSymbolAddress(&p_wqkv, g_wqkv);
    cudaGetSymbolAddress(&p_wproj, g_wproj);
    cudaGetSymbolAddress(&p_w1, g_w1);
    cudaGetSymbolAddress(&p_w2, g_w2);

    static int attn_smem_set = 0;
    // setting an attribute is idempotent & cheap; do it every call (no behavior change)
    cudaFuncSetAttribute(attn_kernel, cudaFuncAttributeMaxDynamicSharedMemorySize,
                         2 * NHEAD * SEQ * HDIM * (int)sizeof(float));
    (void)attn_smem_set;

    const int ATTN_SMEM = 2 * NHEAD * SEQ * HDIM * (int)sizeof(float);  // 51200 B

    // 1) weights -> bf16
    convert_w_kernel<<<768, 256>>>(qkv_w, proj_w, w1, w2);
    // 2) LN1: x -> yb
    ln_kernel<<<NTOK / 8, 256>>>(x, ln1_g, ln1_b, (__nv_bfloat16*)p_yb);
    // 3) qkv GEMM: yb @ wqkv + b -> qkv (bf16)
    gemm_kernel<EPI_BF16><<<dim3(NTOK / 64, D3 / 64), 128>>>(
        (const __nv_bfloat16*)p_yb, (const __nv_bfloat16*)p_wqkv, qkv_b, nullptr, p_qkv, D3, DMODEL);
    // 4) attention
    attn_kernel<<<NSEQ, 256, ATTN_SMEM>>>(logit_scale);
    // 5) proj GEMM + residual -> x2 (fp32)
    gemm_kernel<EPI_PROJ><<<dim3(NTOK / 64, DMODEL / 64), 128>>>(
        (const __nv_bfloat16*)p_attn, (const __nv_bfloat16*)p_wproj, proj_b, x, p_x2, DMODEL, DMODEL);
    // 6) LN2: x2 -> y2
    ln_kernel<<<NTOK / 8, 256>>>((const float*)p_x2, ln2_g, ln2_b, (__nv_bfloat16*)p_y2);
    // 7) ffn1 GEMM + gelu -> hid (bf16)
    gemm_kernel<EPI_GELU><<<dim3(NTOK / 64, DFFN / 64), 128>>>(
        (const __nv_bfloat16*)p_y2, (const __nv_bfloat16*)p_w1, b1, nullptr, p_hid, DFFN, DMODEL);
    // 8) ffn2 GEMM + residual -> out (fp32)
    gemm_kernel<EPI_OUT><<<dim3(NTOK / 64, DMODEL / 64), 128>>>(
        (const __nv_bfloat16*)p_hid, (const __nv_bfloat16*)p_w2, b2, (const float*)p_x2, d_out, DMODEL, DFFN);
}